// round 11
// baseline (speedup 1.0000x reference)
#include <cuda_runtime.h>
#include <cuda_bf16.h>
#include <cstdint>

// Problem constants
#define BB      4
#define NN      10000
#define EE      160000
#define HH      128
#define NHEADS  4
#define HOUT    512      // NHEADS * HH
#define MTOT    (BB*NN)  // 40000 rows

// ---------------------------------------------------------------------------
// Static device scratch
// ---------------------------------------------------------------------------
__device__ float d_Agg[(size_t)BB * NN * HOUT];     // aggregated X, head-major [B*N, 4*128]
__device__ float d_X[(size_t)BB * NN * HH];         // layer activations  [B*N, 128]
__device__ float d_esrc[BB * NN * NHEADS];
__device__ float d_edst[BB * NN * NHEADS];
__device__ float d_alpha[(size_t)BB * EE * NHEADS]; // UNNORMALIZED exp weights
__device__ float d_aself[BB * NN * NHEADS];         // unnormalized self exp
__device__ float d_ainv[BB * NN * NHEADS];          // per-node 1/sum
__device__ int   d_cnt[BB * (NN + 1)];
__device__ int   d_off[BB * (NN + 1)];
__device__ int   d_cur[BB * NN];
__device__ int   d_es [BB * EE];
__device__ float d_Ws[HH * NHEADS];
__device__ float d_Wd[HH * NHEADS];
__device__ __nv_bfloat16 d_WThi[HH * HOUT];         // W^T split, [c=128][k=512], 0.25 folded
__device__ __nv_bfloat16 d_WTlo[HH * HOUT];

__device__ __forceinline__ float lrelu(float x) { return x > 0.f ? x : 0.2f * x; }

__device__ __forceinline__ uint32_t s2u(const void* p) {
    return (uint32_t)__cvta_generic_to_shared(p);
}
__device__ __forceinline__ uint32_t packbf(float x, float y) {
    __nv_bfloat162 t = __floats2bfloat162_rn(x, y);
    return *(uint32_t*)&t;
}
__device__ __forceinline__ void ldsm4(uint32_t* r, uint32_t addr) {
    asm volatile("ldmatrix.sync.aligned.m8n8.x4.shared.b16 {%0,%1,%2,%3}, [%4];\n"
                 : "=r"(r[0]), "=r"(r[1]), "=r"(r[2]), "=r"(r[3]) : "r"(addr));
}
__device__ __forceinline__ void mma16816(float* c, const uint32_t* a, const uint32_t* b) {
    asm volatile("mma.sync.aligned.m16n8k16.row.col.f32.bf16.bf16.f32 "
                 "{%0,%1,%2,%3}, {%4,%5,%6,%7}, {%8,%9}, {%0,%1,%2,%3};\n"
                 : "+f"(c[0]), "+f"(c[1]), "+f"(c[2]), "+f"(c[3])
                 : "r"(a[0]), "r"(a[1]), "r"(a[2]), "r"(a[3]), "r"(b[0]), "r"(b[1]));
}

// ---------------------------------------------------------------------------
// CSR build
// ---------------------------------------------------------------------------
__global__ void k_zero_cnt() {
    int i = blockIdx.x * blockDim.x + threadIdx.x;
    if (i < BB * (NN + 1)) d_cnt[i] = 0;
}
__global__ void k_hist(const int* __restrict__ tgt) {
    int e = blockIdx.x * blockDim.x + threadIdx.x;
    if (e < BB * EE) {
        int b = e / EE;
        atomicAdd(&d_cnt[b * (NN + 1) + tgt[e]], 1);
    }
}
__global__ void k_scan() {
    int b = blockIdx.x;
    __shared__ int sh[1024];
    __shared__ int s_run;
    int tid = threadIdx.x;
    if (tid == 0) s_run = 0;
    __syncthreads();
    for (int base = 0; base < NN; base += 1024) {
        int idx = base + tid;
        int c = (idx < NN) ? d_cnt[b * (NN + 1) + idx] : 0;
        sh[tid] = c;
        __syncthreads();
        #pragma unroll
        for (int st = 1; st < 1024; st <<= 1) {
            int v = (tid >= st) ? sh[tid - st] : 0;
            __syncthreads();
            sh[tid] += v;
            __syncthreads();
        }
        int run = s_run;
        if (idx < NN) {
            int excl = run + sh[tid] - c;
            d_off[b * (NN + 1) + idx] = excl;
            d_cur[b * NN + idx]       = excl;
        }
        __syncthreads();
        if (tid == 1023) s_run = run + sh[1023];
        __syncthreads();
    }
    if (tid == 0) d_off[b * (NN + 1) + NN] = s_run;
}
__global__ void k_scatter(const int* __restrict__ src, const int* __restrict__ tgt) {
    int e = blockIdx.x * blockDim.x + threadIdx.x;
    if (e < BB * EE) {
        int b = e / EE;
        int t = tgt[e];
        int p = atomicAdd(&d_cur[b * NN + t], 1);
        d_es[(size_t)b * EE + p] = src[e];
    }
}

// ---------------------------------------------------------------------------
// Merged per-layer prep:
//  blocks 0..15  : bf16 split of 0.25*W^T  (c = blk*8 + t/32, kb = (t&31)*16)
//  blocks 16..19 : attention projection vectors (t' = (blk-16)*256 + tid)
// ---------------------------------------------------------------------------
__global__ void __launch_bounds__(256) k_prep(const float* __restrict__ W,
                                              const float* __restrict__ as_,
                                              const float* __restrict__ ad_) {
    int blk = blockIdx.x;
    int t = threadIdx.x;
    if (blk < 16) {
        int c = blk * 8 + (t >> 5);
        int kb = (t & 31) * 16;
        __nv_bfloat16 hi[16], lo[16];
        #pragma unroll
        for (int i = 0; i < 16; i++) {
            int k = kb + i;
            float val = 0.25f * W[(size_t)(k & 127) * HOUT + (k >> 7) * HH + c];
            __nv_bfloat16 h = __float2bfloat16_rn(val);
            hi[i] = h;
            lo[i] = __float2bfloat16_rn(val - __bfloat162float(h));
        }
        size_t base = (size_t)c * HOUT + kb;
        *(uint4*)&d_WThi[base]     = *(uint4*)&hi[0];
        *(uint4*)&d_WThi[base + 8] = *(uint4*)&hi[8];
        *(uint4*)&d_WTlo[base]     = *(uint4*)&lo[0];
        *(uint4*)&d_WTlo[base + 8] = *(uint4*)&lo[8];
    } else {
        int tt = (blk - 16) * 256 + t;       // 0..1023
        int c = tt >> 3;
        int q = tt & 7;
        int h = q & 3;
        bool is_d = (q >= 4);
        const float* a = is_d ? ad_ : as_;
        float sum = 0.f;
        const float* wr = W + (size_t)c * HOUT + h * HH;
        const float* ar = a + h * HH;
        #pragma unroll 8
        for (int k = 0; k < HH; k++) sum = fmaf(wr[k], ar[k], sum);
        if (is_d) d_Wd[c * NHEADS + h] = sum;
        else      d_Ws[c * NHEADS + h] = sum;
    }
}

// ---------------------------------------------------------------------------
// escore: warp per row
// ---------------------------------------------------------------------------
__global__ void __launch_bounds__(256) k_escore(const float* __restrict__ Xin) {
    __shared__ float sWs[HH * NHEADS];
    __shared__ float sWd[HH * NHEADS];
    int tid = threadIdx.x;
    sWs[tid] = d_Ws[tid]; sWs[tid + 256] = d_Ws[tid + 256];
    sWd[tid] = d_Wd[tid]; sWd[tid + 256] = d_Wd[tid + 256];
    __syncthreads();

    int row = blockIdx.x * 8 + (tid >> 5);
    int lane = tid & 31;
    float4 x = *(const float4*)&Xin[(size_t)row * HH + lane * 4];
    float xv[4] = {x.x, x.y, x.z, x.w};
    float p[8] = {0, 0, 0, 0, 0, 0, 0, 0};
    #pragma unroll
    for (int i = 0; i < 4; i++) {
        int c = lane * 4 + i;
        #pragma unroll
        for (int h = 0; h < 4; h++) {
            p[h]     = fmaf(xv[i], sWs[c * 4 + h], p[h]);
            p[4 + h] = fmaf(xv[i], sWd[c * 4 + h], p[4 + h]);
        }
    }
    #pragma unroll
    for (int s = 16; s > 0; s >>= 1) {
        #pragma unroll
        for (int q = 0; q < 8; q++)
            p[q] += __shfl_xor_sync(0xffffffffu, p[q], s);
    }
    if (lane == 0) {
        *(float4*)&d_esrc[row * 4] = make_float4(p[0], p[1], p[2], p[3]);
        *(float4*)&d_edst[row * 4] = make_float4(p[4], p[5], p[6], p[7]);
    }
}

// ---------------------------------------------------------------------------
// alpha: warp per node. 2 passes only: pass1 max, pass2 exp+store+sum.
// Normalization deferred to gather via d_ainv.
// ---------------------------------------------------------------------------
__global__ void __launch_bounds__(256) k_alpha() {
    int w = blockIdx.x * 8 + (threadIdx.x >> 5);
    int lane = threadIdx.x & 31;
    int b = w / NN;
    int n = w - b * NN;
    const int beg = d_off[b * (NN + 1) + n];
    const int cnte = d_off[b * (NN + 1) + n + 1] - beg;
    const size_t ebase = (size_t)b * EE + beg;

    float4 ed4 = *(const float4*)&d_edst[w * 4];
    float edv[4] = {ed4.x, ed4.y, ed4.z, ed4.w};
    float4 es4 = *(const float4*)&d_esrc[w * 4];
    float esf[4] = {es4.x, es4.y, es4.z, es4.w};
    float e_self[4];
    #pragma unroll
    for (int h = 0; h < 4; h++) e_self[h] = lrelu(esf[h] + edv[h]);

    // pass 1: max
    float mx[4] = {e_self[0], e_self[1], e_self[2], e_self[3]};
    for (int j = lane; j < cnte; j += 32) {
        int src = __ldg(&d_es[ebase + j]);
        float4 e4 = __ldg((const float4*)&d_esrc[((size_t)b * NN + src) * 4]);
        float ev[4] = {e4.x, e4.y, e4.z, e4.w};
        #pragma unroll
        for (int h = 0; h < 4; h++) mx[h] = fmaxf(mx[h], lrelu(ev[h] + edv[h]));
    }
    #pragma unroll
    for (int s = 16; s > 0; s >>= 1)
        #pragma unroll
        for (int h = 0; h < 4; h++) mx[h] = fmaxf(mx[h], __shfl_xor_sync(0xffffffffu, mx[h], s));

    // pass 2: exp, store unnormalized, accumulate sum
    float sm[4] = {0, 0, 0, 0};
    for (int j = lane; j < cnte; j += 32) {
        int src = __ldg(&d_es[ebase + j]);
        float4 e4 = __ldg((const float4*)&d_esrc[((size_t)b * NN + src) * 4]);
        float ev[4] = {e4.x, e4.y, e4.z, e4.w};
        float ex[4];
        #pragma unroll
        for (int h = 0; h < 4; h++) {
            ex[h] = __expf(lrelu(ev[h] + edv[h]) - mx[h]);
            sm[h] += ex[h];
        }
        *(float4*)&d_alpha[(ebase + j) * 4] = make_float4(ex[0], ex[1], ex[2], ex[3]);
    }
    #pragma unroll
    for (int s = 16; s > 0; s >>= 1)
        #pragma unroll
        for (int h = 0; h < 4; h++) sm[h] += __shfl_xor_sync(0xffffffffu, sm[h], s);

    if (lane == 0) {
        float ex_self[4], inv[4];
        #pragma unroll
        for (int h = 0; h < 4; h++) {
            ex_self[h] = __expf(e_self[h] - mx[h]);
            inv[h] = 1.f / (sm[h] + ex_self[h]);
        }
        *(float4*)&d_aself[w * 4] = make_float4(ex_self[0], ex_self[1], ex_self[2], ex_self[3]);
        *(float4*)&d_ainv[w * 4]  = make_float4(inv[0], inv[1], inv[2], inv[3]);
    }
}

// ---------------------------------------------------------------------------
// gather: 128 threads = 4 warps, edge-parallel with smem-staged src indices
// (kills the LDG->LDG dependent chain). Final multiply by d_ainv.
// ---------------------------------------------------------------------------
__global__ void __launch_bounds__(128) k_gather(const float* __restrict__ Xin) {
    const int w = blockIdx.x;
    const int tid = threadIdx.x;
    const int wp = tid >> 5;
    const int lane = tid & 31;
    const int b = w / NN;
    const int n = w - b * NN;
    const int beg = d_off[b * (NN + 1) + n];
    const int cnte = d_off[b * (NN + 1) + n + 1] - beg;
    const size_t ebase = (size_t)b * EE + beg;
    const float* Xb = Xin + (size_t)b * NN * HH;

    __shared__ int ssrc[128];

    float4 a0 = make_float4(0, 0, 0, 0);
    float4 a1 = make_float4(0, 0, 0, 0);
    float4 a2 = make_float4(0, 0, 0, 0);
    float4 a3 = make_float4(0, 0, 0, 0);

    if (wp == 0) {
        float4 as_ = __ldg((const float4*)&d_aself[w * 4]);
        float4 xs = __ldg((const float4*)&Xb[(size_t)n * HH + lane * 4]);
        a0.x = as_.x * xs.x; a0.y = as_.x * xs.y; a0.z = as_.x * xs.z; a0.w = as_.x * xs.w;
        a1.x = as_.y * xs.x; a1.y = as_.y * xs.y; a1.z = as_.y * xs.z; a1.w = as_.y * xs.w;
        a2.x = as_.z * xs.x; a2.y = as_.z * xs.y; a2.z = as_.z * xs.z; a2.w = as_.z * xs.w;
        a3.x = as_.w * xs.x; a3.y = as_.w * xs.y; a3.z = as_.w * xs.z; a3.w = as_.w * xs.w;
    }

    for (int cb = 0; cb < cnte; cb += 128) {
        int m = min(128, cnte - cb);
        if (tid < m) ssrc[tid] = __ldg(&d_es[ebase + cb + tid]);
        __syncthreads();
        #pragma unroll 4
        for (int j = wp; j < m; j += 4) {
            int src = ssrc[j];
            float4 al = __ldg((const float4*)&d_alpha[(ebase + cb + j) * 4]);
            float4 x = __ldg((const float4*)&Xb[(size_t)src * HH + lane * 4]);
            a0.x = fmaf(al.x, x.x, a0.x); a0.y = fmaf(al.x, x.y, a0.y);
            a0.z = fmaf(al.x, x.z, a0.z); a0.w = fmaf(al.x, x.w, a0.w);
            a1.x = fmaf(al.y, x.x, a1.x); a1.y = fmaf(al.y, x.y, a1.y);
            a1.z = fmaf(al.y, x.z, a1.z); a1.w = fmaf(al.y, x.w, a1.w);
            a2.x = fmaf(al.z, x.x, a2.x); a2.y = fmaf(al.z, x.y, a2.y);
            a2.z = fmaf(al.z, x.z, a2.z); a2.w = fmaf(al.z, x.w, a2.w);
            a3.x = fmaf(al.w, x.x, a3.x); a3.y = fmaf(al.w, x.y, a3.y);
            a3.z = fmaf(al.w, x.z, a3.z); a3.w = fmaf(al.w, x.w, a3.w);
        }
        __syncthreads();
    }

    __shared__ float4 s[4][4][32];      // [warp][head][lane]
    s[wp][0][lane] = a0;
    s[wp][1][lane] = a1;
    s[wp][2][lane] = a2;
    s[wp][3][lane] = a3;
    __syncthreads();

    int h = wp;
    float inv = __ldg(&d_ainv[w * 4 + h]);
    float4 r0 = s[0][h][lane], r1 = s[1][h][lane], r2 = s[2][h][lane], r3 = s[3][h][lane];
    float4 r;
    r.x = ((r0.x + r1.x) + (r2.x + r3.x)) * inv;
    r.y = ((r0.y + r1.y) + (r2.y + r3.y)) * inv;
    r.z = ((r0.z + r1.z) + (r2.z + r3.z)) * inv;
    r.w = ((r0.w + r1.w) + (r2.w + r3.w)) * inv;
    *(float4*)&d_Agg[(size_t)w * HOUT + h * HH + lane * 4] = r;
}

// ---------------------------------------------------------------------------
// Tensor-core GEMM + fused epilogue (bias, LN+ReLU or raw out).
// ---------------------------------------------------------------------------
#define SPAD 40
__global__ void __launch_bounds__(256) k_gemm_tc(const float* __restrict__ bias,
                                                 const float* __restrict__ g,
                                                 const float* __restrict__ bparm,
                                                 float* __restrict__ outp,
                                                 int mode) {
    __shared__ __nv_bfloat16 sAhi[128 * SPAD];
    __shared__ __nv_bfloat16 sAlo[128 * SPAD];
    __shared__ __nv_bfloat16 sBhi[128 * SPAD];
    __shared__ __nv_bfloat16 sBlo[128 * SPAD];
    __shared__ float sred[2][2][128];

    const int tid  = threadIdx.x;
    const int lane = tid & 31;
    const int wid  = tid >> 5;
    const int wm   = wid & 3;
    const int wn   = wid >> 2;
    const int brow = blockIdx.x * 128;

    const int lr = tid >> 1;
    const int lk = (tid & 1) * 16;
    const int grow = brow + lr;
    const bool arow_ok = (grow < MTOT);

    float c[2][8][4];
    #pragma unroll
    for (int i = 0; i < 2; i++)
        #pragma unroll
        for (int j = 0; j < 8; j++)
            #pragma unroll
            for (int q = 0; q < 4; q++) c[i][j][q] = 0.f;

    const uint32_t uAhi = s2u(sAhi), uAlo = s2u(sAlo);
    const uint32_t uBhi = s2u(sBhi), uBlo = s2u(sBlo);

    float4 a0, a1, a2, a3;
    uint4 bh0, bh1, bl0, bl1;

    {
        if (arow_ok) {
            const float* pa = &d_Agg[(size_t)grow * HOUT + lk];
            a0 = *(const float4*)(pa);     a1 = *(const float4*)(pa + 4);
            a2 = *(const float4*)(pa + 8); a3 = *(const float4*)(pa + 12);
        } else {
            a0 = a1 = a2 = a3 = make_float4(0, 0, 0, 0);
        }
        const uint4* pbh = (const uint4*)&d_WThi[(size_t)lr * HOUT + lk];
        const uint4* pbl = (const uint4*)&d_WTlo[(size_t)lr * HOUT + lk];
        bh0 = pbh[0]; bh1 = pbh[1];
        bl0 = pbl[0]; bl1 = pbl[1];
    }

    #pragma unroll 1
    for (int it = 0; it < HOUT / 32; it++) {
        {
            float af[16] = {a0.x, a0.y, a0.z, a0.w, a1.x, a1.y, a1.z, a1.w,
                            a2.x, a2.y, a2.z, a2.w, a3.x, a3.y, a3.z, a3.w};
            uint32_t phi[8], plo[8];
            #pragma unroll
            for (int i = 0; i < 8; i++) {
                float f0 = af[2 * i], f1 = af[2 * i + 1];
                __nv_bfloat16 h0 = __float2bfloat16_rn(f0);
                __nv_bfloat16 h1 = __float2bfloat16_rn(f1);
                phi[i] = packbf(f0, f1);
                plo[i] = packbf(f0 - __bfloat162float(h0), f1 - __bfloat162float(h1));
            }
            int so = lr * SPAD + lk;
            *(uint4*)&sAhi[so]     = make_uint4(phi[0], phi[1], phi[2], phi[3]);
            *(uint4*)&sAhi[so + 8] = make_uint4(phi[4], phi[5], phi[6], phi[7]);
            *(uint4*)&sAlo[so]     = make_uint4(plo[0], plo[1], plo[2], plo[3]);
            *(uint4*)&sAlo[so + 8] = make_uint4(plo[4], plo[5], plo[6], plo[7]);
            *(uint4*)&sBhi[so]     = bh0;
            *(uint4*)&sBhi[so + 8] = bh1;
            *(uint4*)&sBlo[so]     = bl0;
            *(uint4*)&sBlo[so + 8] = bl1;
        }
        __syncthreads();

        if (it + 1 < HOUT / 32) {
            int k0 = (it + 1) * 32;
            if (arow_ok) {
                const float* pa = &d_Agg[(size_t)grow * HOUT + k0 + lk];
                a0 = *(const float4*)(pa);     a1 = *(const float4*)(pa + 4);
                a2 = *(const float4*)(pa + 8); a3 = *(const float4*)(pa + 12);
            }
            const uint4* pbh = (const uint4*)&d_WThi[(size_t)lr * HOUT + k0 + lk];
            const uint4* pbl = (const uint4*)&d_WTlo[(size_t)lr * HOUT + k0 + lk];
            bh0 = pbh[0]; bh1 = pbh[1];
            bl0 = pbl[0]; bl1 = pbl[1];
        }

        #pragma unroll
        for (int ks = 0; ks < 2; ks++) {
            const int kk = ks * 16;
            uint32_t ahi[2][4], alo[2][4];
            #pragma unroll
            for (int mt = 0; mt < 2; mt++) {
                int rb = wm * 32 + mt * 16;
                uint32_t off = 2u * ((rb + (lane & 15)) * SPAD + kk + (lane >> 4) * 8);
                ldsm4(ahi[mt], uAhi + off);
                ldsm4(alo[mt], uAlo + off);
            }
            #pragma unroll
            for (int np = 0; np < 4; np++) {
                int cb = wn * 64 + np * 16;
                uint32_t boff = 2u * ((cb + (lane >> 4) * 8 + (lane & 7)) * SPAD
                                      + kk + ((lane >> 3) & 1) * 8);
                uint32_t bh[4], bl[4];
                ldsm4(bh, uBhi + boff);
                ldsm4(bl, uBlo + boff);
                #pragma unroll
                for (int half = 0; half < 2; half++) {
                    int nt = np * 2 + half;
                    #pragma unroll
                    for (int mt = 0; mt < 2; mt++) {
                        mma16816(c[mt][nt], ahi[mt], &bh[half * 2]);
                        mma16816(c[mt][nt], ahi[mt], &bl[half * 2]);
                        mma16816(c[mt][nt], alo[mt], &bh[half * 2]);
                    }
                }
            }
        }
        __syncthreads();
    }

    // ---- fused epilogue ----
    const int colq = (lane & 3) * 2;

    #pragma unroll
    for (int nt = 0; nt < 8; nt++) {
        int col = wn * 64 + nt * 8 + colq;
        float b0 = __ldg(&bias[col]);
        float b1 = __ldg(&bias[col + 1]);
        #pragma unroll
        for (int mt = 0; mt < 2; mt++) {
            c[mt][nt][0] += b0; c[mt][nt][1] += b1;
            c[mt][nt][2] += b0; c[mt][nt][3] += b1;
        }
    }

    if (mode == 1) {
        #pragma unroll
        for (int mt = 0; mt < 2; mt++) {
            #pragma unroll
            for (int nt = 0; nt < 8; nt++) {
                int r0 = brow + wm * 32 + mt * 16 + (lane >> 2);
                int col = wn * 64 + nt * 8 + colq;
                if (r0 < MTOT)
                    *(float2*)&outp[(size_t)r0 * HH + col] = make_float2(c[mt][nt][0], c[mt][nt][1]);
                if (r0 + 8 < MTOT)
                    *(float2*)&outp[(size_t)(r0 + 8) * HH + col] = make_float2(c[mt][nt][2], c[mt][nt][3]);
            }
        }
        return;
    }

    // mean
    #pragma unroll
    for (int mt = 0; mt < 2; mt++) {
        float p0 = 0.f, p1 = 0.f;
        #pragma unroll
        for (int nt = 0; nt < 8; nt++) {
            p0 += c[mt][nt][0] + c[mt][nt][1];
            p1 += c[mt][nt][2] + c[mt][nt][3];
        }
        p0 += __shfl_xor_sync(0xffffffffu, p0, 1);
        p0 += __shfl_xor_sync(0xffffffffu, p0, 2);
        p1 += __shfl_xor_sync(0xffffffffu, p1, 1);
        p1 += __shfl_xor_sync(0xffffffffu, p1, 2);
        if ((lane & 3) == 0) {
            int r = wm * 32 + mt * 16 + (lane >> 2);
            sred[0][wn][r]     = p0;
            sred[0][wn][r + 8] = p1;
        }
    }
    __syncthreads();
    float mu[2][2];
    #pragma unroll
    for (int mt = 0; mt < 2; mt++) {
        int r = wm * 32 + mt * 16 + (lane >> 2);
        mu[mt][0] = (sred[0][0][r]     + sred[0][1][r])     * (1.f / 128.f);
        mu[mt][1] = (sred[0][0][r + 8] + sred[0][1][r + 8]) * (1.f / 128.f);
    }

    // variance
    #pragma unroll
    for (int mt = 0; mt < 2; mt++) {
        float p0 = 0.f, p1 = 0.f;
        #pragma unroll
        for (int nt = 0; nt < 8; nt++) {
            float d0 = c[mt][nt][0] - mu[mt][0];
            float d1 = c[mt][nt][1] - mu[mt][0];
            float d2 = c[mt][nt][2] - mu[mt][1];
            float d3 = c[mt][nt][3] - mu[mt][1];
            p0 += d0 * d0 + d1 * d1;
            p1 += d2 * d2 + d3 * d3;
        }
        p0 += __shfl_xor_sync(0xffffffffu, p0, 1);
        p0 += __shfl_xor_sync(0xffffffffu, p0, 2);
        p1 += __shfl_xor_sync(0xffffffffu, p1, 1);
        p1 += __shfl_xor_sync(0xffffffffu, p1, 2);
        if ((lane & 3) == 0) {
            int r = wm * 32 + mt * 16 + (lane >> 2);
            sred[1][wn][r]     = p0;
            sred[1][wn][r + 8] = p1;
        }
    }
    __syncthreads();
    float rst[2][2];
    #pragma unroll
    for (int mt = 0; mt < 2; mt++) {
        int r = wm * 32 + mt * 16 + (lane >> 2);
        rst[mt][0] = rsqrtf((sred[1][0][r]     + sred[1][1][r])     * (1.f / 128.f) + 1e-5f);
        rst[mt][1] = rsqrtf((sred[1][0][r + 8] + sred[1][1][r + 8]) * (1.f / 128.f) + 1e-5f);
    }

    // normalize + ReLU + store
    #pragma unroll
    for (int nt = 0; nt < 8; nt++) {
        int col = wn * 64 + nt * 8 + colq;
        float g0 = __ldg(&g[col]),      g1 = __ldg(&g[col + 1]);
        float q0 = __ldg(&bparm[col]),  q1 = __ldg(&bparm[col + 1]);
        #pragma unroll
        for (int mt = 0; mt < 2; mt++) {
            int r0 = brow + wm * 32 + mt * 16 + (lane >> 2);
            if (r0 < MTOT) {
                float o0 = fmaxf(fmaf((c[mt][nt][0] - mu[mt][0]) * rst[mt][0], g0, q0), 0.f);
                float o1 = fmaxf(fmaf((c[mt][nt][1] - mu[mt][0]) * rst[mt][0], g1, q1), 0.f);
                *(float2*)&d_X[(size_t)r0 * HH + col] = make_float2(o0, o1);
            }
            if (r0 + 8 < MTOT) {
                float o2 = fmaxf(fmaf((c[mt][nt][2] - mu[mt][1]) * rst[mt][1], g0, q0), 0.f);
                float o3 = fmaxf(fmaf((c[mt][nt][3] - mu[mt][1]) * rst[mt][1], g1, q1), 0.f);
                *(float2*)&d_X[(size_t)(r0 + 8) * HH + col] = make_float2(o2, o3);
            }
        }
    }
}

// ---------------------------------------------------------------------------
// Launch
// ---------------------------------------------------------------------------
extern "C" void kernel_launch(void* const* d_in, const int* in_sizes, int n_in,
                              void* d_out, int out_size) {
    const float* x0   = (const float*)d_in[0];
    const int*   src  = (const int*)d_in[1];
    const int*   tgt  = (const int*)d_in[2];
    const float* W1   = (const float*)d_in[3];
    const float* as1  = (const float*)d_in[4];
    const float* ad1  = (const float*)d_in[5];
    const float* b1   = (const float*)d_in[6];
    const float* W2   = (const float*)d_in[7];
    const float* as2  = (const float*)d_in[8];
    const float* ad2  = (const float*)d_in[9];
    const float* b2   = (const float*)d_in[10];
    const float* W3   = (const float*)d_in[11];
    const float* as3  = (const float*)d_in[12];
    const float* ad3  = (const float*)d_in[13];
    const float* b3   = (const float*)d_in[14];
    const float* g1   = (const float*)d_in[15];
    const float* bb1  = (const float*)d_in[16];
    const float* g2   = (const float*)d_in[17];
    const float* bb2  = (const float*)d_in[18];
    float* out = (float*)d_out;

    float* d_X_ptr;
    cudaGetSymbolAddress((void**)&d_X_ptr, d_X);

    // ---- CSR build ----
    k_zero_cnt<<<(BB * (NN + 1) + 255) / 256, 256>>>();
    k_hist<<<(BB * EE + 255) / 256, 256>>>(tgt);
    k_scan<<<BB, 1024>>>();
    k_scatter<<<(BB * EE + 255) / 256, 256>>>(src, tgt);

    const int gw = MTOT / 8;
    const int gm = (MTOT + 127) / 128;

    // ---- Layer 1 ----
    k_prep<<<20, 256>>>(W1, as1, ad1);
    k_escore<<<gw, 256>>>(x0);
    k_alpha<<<gw, 256>>>();
    k_gather<<<MTOT, 128>>>(x0);
    k_gemm_tc<<<gm, 256>>>(b1, g1, bb1, nullptr, 0);

    // ---- Layer 2 ----
    k_prep<<<20, 256>>>(W2, as2, ad2);
    k_escore<<<gw, 256>>>(d_X_ptr);
    k_alpha<<<gw, 256>>>();
    k_gather<<<MTOT, 128>>>(d_X_ptr);
    k_gemm_tc<<<gm, 256>>>(b2, g2, bb2, nullptr, 0);

    // ---- Layer 3 ----
    k_prep<<<20, 256>>>(W3, as3, ad3);
    k_escore<<<gw, 256>>>(d_X_ptr);
    k_alpha<<<gw, 256>>>();
    k_gather<<<MTOT, 128>>>(d_X_ptr);
    k_gemm_tc<<<gm, 256>>>(b3, nullptr, nullptr, out, 1);
}

// round 12
// speedup vs baseline: 1.0466x; 1.0466x over previous
#include <cuda_runtime.h>
#include <cuda_bf16.h>
#include <cstdint>

// Problem constants
#define BB      4
#define NN      10000
#define EE      160000
#define HH      128
#define NHEADS  4
#define HOUT    512      // NHEADS * HH
#define MTOT    (BB*NN)  // 40000 rows

// ---------------------------------------------------------------------------
// Static device scratch
// ---------------------------------------------------------------------------
__device__ __nv_bfloat16 d_Agghi[(size_t)BB * NN * HOUT]; // aggregated X, bf16 hi
__device__ __nv_bfloat16 d_Agglo[(size_t)BB * NN * HOUT]; // aggregated X, bf16 lo
__device__ float d_X[(size_t)BB * NN * HH];         // layer activations  [B*N, 128]
__device__ float d_esrc[BB * NN * NHEADS];
__device__ float d_edst[BB * NN * NHEADS];
__device__ float d_alpha[(size_t)BB * EE * NHEADS]; // normalized softmax weights
__device__ float d_aself[BB * NN * NHEADS];         // normalized self weights
__device__ int   d_cnt[BB * (NN + 1)];
__device__ int   d_off[BB * (NN + 1)];
__device__ int   d_cur[BB * NN];
__device__ int   d_es [BB * EE];
__device__ float d_Ws[HH * NHEADS];
__device__ float d_Wd[HH * NHEADS];
__device__ __nv_bfloat16 d_WThi[HH * HOUT];         // W^T split, [c=128][k=512], 0.25 folded
__device__ __nv_bfloat16 d_WTlo[HH * HOUT];

__device__ __forceinline__ float lrelu(float x) { return x > 0.f ? x : 0.2f * x; }

__device__ __forceinline__ uint32_t s2u(const void* p) {
    return (uint32_t)__cvta_generic_to_shared(p);
}
__device__ __forceinline__ uint32_t packbf(float x, float y) {
    __nv_bfloat162 t = __floats2bfloat162_rn(x, y);
    return *(uint32_t*)&t;
}
__device__ __forceinline__ void ldsm4(uint32_t* r, uint32_t addr) {
    asm volatile("ldmatrix.sync.aligned.m8n8.x4.shared.b16 {%0,%1,%2,%3}, [%4];\n"
                 : "=r"(r[0]), "=r"(r[1]), "=r"(r[2]), "=r"(r[3]) : "r"(addr));
}
__device__ __forceinline__ void mma16816(float* c, const uint32_t* a, const uint32_t* b) {
    asm volatile("mma.sync.aligned.m16n8k16.row.col.f32.bf16.bf16.f32 "
                 "{%0,%1,%2,%3}, {%4,%5,%6,%7}, {%8,%9}, {%0,%1,%2,%3};\n"
                 : "+f"(c[0]), "+f"(c[1]), "+f"(c[2]), "+f"(c[3])
                 : "r"(a[0]), "r"(a[1]), "r"(a[2]), "r"(a[3]), "r"(b[0]), "r"(b[1]));
}

// ---------------------------------------------------------------------------
// CSR build
// ---------------------------------------------------------------------------
__global__ void k_zero_cnt() {
    int i = blockIdx.x * blockDim.x + threadIdx.x;
    if (i < BB * (NN + 1)) d_cnt[i] = 0;
}
__global__ void k_hist(const int* __restrict__ tgt) {
    int e = blockIdx.x * blockDim.x + threadIdx.x;
    if (e < BB * EE) {
        int b = e / EE;
        atomicAdd(&d_cnt[b * (NN + 1) + tgt[e]], 1);
    }
}
__global__ void k_scan() {
    int b = blockIdx.x;
    __shared__ int sh[1024];
    __shared__ int s_run;
    int tid = threadIdx.x;
    if (tid == 0) s_run = 0;
    __syncthreads();
    for (int base = 0; base < NN; base += 1024) {
        int idx = base + tid;
        int c = (idx < NN) ? d_cnt[b * (NN + 1) + idx] : 0;
        sh[tid] = c;
        __syncthreads();
        #pragma unroll
        for (int st = 1; st < 1024; st <<= 1) {
            int v = (tid >= st) ? sh[tid - st] : 0;
            __syncthreads();
            sh[tid] += v;
            __syncthreads();
        }
        int run = s_run;
        if (idx < NN) {
            int excl = run + sh[tid] - c;
            d_off[b * (NN + 1) + idx] = excl;
            d_cur[b * NN + idx]       = excl;
        }
        __syncthreads();
        if (tid == 1023) s_run = run + sh[1023];
        __syncthreads();
    }
    if (tid == 0) d_off[b * (NN + 1) + NN] = s_run;
}
__global__ void k_scatter(const int* __restrict__ src, const int* __restrict__ tgt) {
    int e = blockIdx.x * blockDim.x + threadIdx.x;
    if (e < BB * EE) {
        int b = e / EE;
        int t = tgt[e];
        int p = atomicAdd(&d_cur[b * NN + t], 1);
        d_es[(size_t)b * EE + p] = src[e];
    }
}

// ---------------------------------------------------------------------------
// Merged per-layer prep:
//  blocks 0..15  : bf16 split of 0.25*W^T
//  blocks 16..19 : attention projection vectors
// ---------------------------------------------------------------------------
__global__ void __launch_bounds__(256) k_prep(const float* __restrict__ W,
                                              const float* __restrict__ as_,
                                              const float* __restrict__ ad_) {
    int blk = blockIdx.x;
    int t = threadIdx.x;
    if (blk < 16) {
        int c = blk * 8 + (t >> 5);
        int kb = (t & 31) * 16;
        __nv_bfloat16 hi[16], lo[16];
        #pragma unroll
        for (int i = 0; i < 16; i++) {
            int k = kb + i;
            float val = 0.25f * W[(size_t)(k & 127) * HOUT + (k >> 7) * HH + c];
            __nv_bfloat16 h = __float2bfloat16_rn(val);
            hi[i] = h;
            lo[i] = __float2bfloat16_rn(val - __bfloat162float(h));
        }
        size_t base = (size_t)c * HOUT + kb;
        *(uint4*)&d_WThi[base]     = *(uint4*)&hi[0];
        *(uint4*)&d_WThi[base + 8] = *(uint4*)&hi[8];
        *(uint4*)&d_WTlo[base]     = *(uint4*)&lo[0];
        *(uint4*)&d_WTlo[base + 8] = *(uint4*)&lo[8];
    } else {
        int tt = (blk - 16) * 256 + t;       // 0..1023
        int c = tt >> 3;
        int q = tt & 7;
        int h = q & 3;
        bool is_d = (q >= 4);
        const float* a = is_d ? ad_ : as_;
        float sum = 0.f;
        const float* wr = W + (size_t)c * HOUT + h * HH;
        const float* ar = a + h * HH;
        #pragma unroll 8
        for (int k = 0; k < HH; k++) sum = fmaf(wr[k], ar[k], sum);
        if (is_d) d_Wd[c * NHEADS + h] = sum;
        else      d_Ws[c * NHEADS + h] = sum;
    }
}

// ---------------------------------------------------------------------------
// escore: warp per row
// ---------------------------------------------------------------------------
__global__ void __launch_bounds__(256) k_escore(const float* __restrict__ Xin) {
    __shared__ float sWs[HH * NHEADS];
    __shared__ float sWd[HH * NHEADS];
    int tid = threadIdx.x;
    sWs[tid] = d_Ws[tid]; sWs[tid + 256] = d_Ws[tid + 256];
    sWd[tid] = d_Wd[tid]; sWd[tid + 256] = d_Wd[tid + 256];
    __syncthreads();

    int row = blockIdx.x * 8 + (tid >> 5);
    int lane = tid & 31;
    float4 x = *(const float4*)&Xin[(size_t)row * HH + lane * 4];
    float xv[4] = {x.x, x.y, x.z, x.w};
    float p[8] = {0, 0, 0, 0, 0, 0, 0, 0};
    #pragma unroll
    for (int i = 0; i < 4; i++) {
        int c = lane * 4 + i;
        #pragma unroll
        for (int h = 0; h < 4; h++) {
            p[h]     = fmaf(xv[i], sWs[c * 4 + h], p[h]);
            p[4 + h] = fmaf(xv[i], sWd[c * 4 + h], p[4 + h]);
        }
    }
    #pragma unroll
    for (int s = 16; s > 0; s >>= 1) {
        #pragma unroll
        for (int q = 0; q < 8; q++)
            p[q] += __shfl_xor_sync(0xffffffffu, p[q], s);
    }
    if (lane == 0) {
        *(float4*)&d_esrc[row * 4] = make_float4(p[0], p[1], p[2], p[3]);
        *(float4*)&d_edst[row * 4] = make_float4(p[4], p[5], p[6], p[7]);
    }
}

// ---------------------------------------------------------------------------
// alpha: warp per node. 3 streamed passes (R7-proven structure).
// ---------------------------------------------------------------------------
__global__ void __launch_bounds__(256) k_alpha() {
    int w = blockIdx.x * 8 + (threadIdx.x >> 5);
    int lane = threadIdx.x & 31;
    int b = w / NN;
    int n = w - b * NN;
    const int beg = d_off[b * (NN + 1) + n];
    const int cnte = d_off[b * (NN + 1) + n + 1] - beg;
    const size_t ebase = (size_t)b * EE + beg;

    float4 ed4 = *(const float4*)&d_edst[w * 4];
    float edv[4] = {ed4.x, ed4.y, ed4.z, ed4.w};
    float4 es4 = *(const float4*)&d_esrc[w * 4];
    float esf[4] = {es4.x, es4.y, es4.z, es4.w};
    float e_self[4];
    #pragma unroll
    for (int h = 0; h < 4; h++) e_self[h] = lrelu(esf[h] + edv[h]);

    // pass 1: max
    float mx[4] = {e_self[0], e_self[1], e_self[2], e_self[3]};
    for (int j = lane; j < cnte; j += 32) {
        int src = __ldg(&d_es[ebase + j]);
        float4 e4 = __ldg((const float4*)&d_esrc[((size_t)b * NN + src) * 4]);
        float ev[4] = {e4.x, e4.y, e4.z, e4.w};
        #pragma unroll
        for (int h = 0; h < 4; h++) mx[h] = fmaxf(mx[h], lrelu(ev[h] + edv[h]));
    }
    #pragma unroll
    for (int s = 16; s > 0; s >>= 1)
        #pragma unroll
        for (int h = 0; h < 4; h++) mx[h] = fmaxf(mx[h], __shfl_xor_sync(0xffffffffu, mx[h], s));

    // pass 2: exp, store to d_alpha, accumulate sum
    float sm[4] = {0, 0, 0, 0};
    for (int j = lane; j < cnte; j += 32) {
        int src = __ldg(&d_es[ebase + j]);
        float4 e4 = __ldg((const float4*)&d_esrc[((size_t)b * NN + src) * 4]);
        float ev[4] = {e4.x, e4.y, e4.z, e4.w};
        float ex[4];
        #pragma unroll
        for (int h = 0; h < 4; h++) {
            ex[h] = __expf(lrelu(ev[h] + edv[h]) - mx[h]);
            sm[h] += ex[h];
        }
        *(float4*)&d_alpha[(ebase + j) * 4] = make_float4(ex[0], ex[1], ex[2], ex[3]);
    }
    #pragma unroll
    for (int s = 16; s > 0; s >>= 1)
        #pragma unroll
        for (int h = 0; h < 4; h++) sm[h] += __shfl_xor_sync(0xffffffffu, sm[h], s);

    float ex_self[4], inv[4];
    #pragma unroll
    for (int h = 0; h < 4; h++) {
        ex_self[h] = __expf(e_self[h] - mx[h]);
        inv[h] = 1.f / (sm[h] + ex_self[h]);
    }
    float4 invv = make_float4(inv[0], inv[1], inv[2], inv[3]);

    // pass 3: rescale stored exps
    for (int j = lane; j < cnte; j += 32) {
        float4 a = *(const float4*)&d_alpha[(ebase + j) * 4];
        a.x *= invv.x; a.y *= invv.y; a.z *= invv.z; a.w *= invv.w;
        *(float4*)&d_alpha[(ebase + j) * 4] = a;
    }
    if (lane == 0)
        *(float4*)&d_aself[w * 4] = make_float4(ex_self[0] * invv.x, ex_self[1] * invv.y,
                                                ex_self[2] * invv.z, ex_self[3] * invv.w);
}

// ---------------------------------------------------------------------------
// gather: 128 threads = 4 warps, edge-parallel (R7 structure). Final write is
// a bf16 hi/lo split of the fp32 accumulator (identical rounding to the old
// in-GEMM split).
// ---------------------------------------------------------------------------
__global__ void __launch_bounds__(128) k_gather(const float* __restrict__ Xin) {
    const int w = blockIdx.x;
    const int wp = threadIdx.x >> 5;
    const int lane = threadIdx.x & 31;
    const int b = w / NN;
    const int n = w - b * NN;
    const int beg = d_off[b * (NN + 1) + n];
    const int cnte = d_off[b * (NN + 1) + n + 1] - beg;
    const size_t ebase = (size_t)b * EE + beg;
    const float* Xb = Xin + (size_t)b * NN * HH;

    float4 a0 = make_float4(0, 0, 0, 0);
    float4 a1 = make_float4(0, 0, 0, 0);
    float4 a2 = make_float4(0, 0, 0, 0);
    float4 a3 = make_float4(0, 0, 0, 0);

    if (wp == 0) {
        float4 as_ = __ldg((const float4*)&d_aself[w * 4]);
        float4 xs = __ldg((const float4*)&Xb[(size_t)n * HH + lane * 4]);
        a0.x = as_.x * xs.x; a0.y = as_.x * xs.y; a0.z = as_.x * xs.z; a0.w = as_.x * xs.w;
        a1.x = as_.y * xs.x; a1.y = as_.y * xs.y; a1.z = as_.y * xs.z; a1.w = as_.y * xs.w;
        a2.x = as_.z * xs.x; a2.y = as_.z * xs.y; a2.z = as_.z * xs.z; a2.w = as_.z * xs.w;
        a3.x = as_.w * xs.x; a3.y = as_.w * xs.y; a3.z = as_.w * xs.z; a3.w = as_.w * xs.w;
    }

    #pragma unroll 2
    for (int j = wp; j < cnte; j += 4) {
        int src = __ldg(&d_es[ebase + j]);
        float4 al = __ldg((const float4*)&d_alpha[(ebase + j) * 4]);
        float4 x = __ldg((const float4*)&Xb[(size_t)src * HH + lane * 4]);
        a0.x = fmaf(al.x, x.x, a0.x); a0.y = fmaf(al.x, x.y, a0.y);
        a0.z = fmaf(al.x, x.z, a0.z); a0.w = fmaf(al.x, x.w, a0.w);
        a1.x = fmaf(al.y, x.x, a1.x); a1.y = fmaf(al.y, x.y, a1.y);
        a1.z = fmaf(al.y, x.z, a1.z); a1.w = fmaf(al.y, x.w, a1.w);
        a2.x = fmaf(al.z, x.x, a2.x); a2.y = fmaf(al.z, x.y, a2.y);
        a2.z = fmaf(al.z, x.z, a2.z); a2.w = fmaf(al.z, x.w, a2.w);
        a3.x = fmaf(al.w, x.x, a3.x); a3.y = fmaf(al.w, x.y, a3.y);
        a3.z = fmaf(al.w, x.z, a3.z); a3.w = fmaf(al.w, x.w, a3.w);
    }

    __shared__ float4 s[4][4][32];      // [warp][head][lane]
    s[wp][0][lane] = a0;
    s[wp][1][lane] = a1;
    s[wp][2][lane] = a2;
    s[wp][3][lane] = a3;
    __syncthreads();

    int h = wp;
    float4 r0 = s[0][h][lane], r1 = s[1][h][lane], r2 = s[2][h][lane], r3 = s[3][h][lane];
    float4 r;
    r.x = (r0.x + r1.x) + (r2.x + r3.x);
    r.y = (r0.y + r1.y) + (r2.y + r3.y);
    r.z = (r0.z + r1.z) + (r2.z + r3.z);
    r.w = (r0.w + r1.w) + (r2.w + r3.w);

    // bf16 hi/lo split (same rounding as old in-GEMM split)
    float hx = __bfloat162float(__float2bfloat16_rn(r.x));
    float hy = __bfloat162float(__float2bfloat16_rn(r.y));
    float hz = __bfloat162float(__float2bfloat16_rn(r.z));
    float hw = __bfloat162float(__float2bfloat16_rn(r.w));
    uint32_t hi01 = packbf(r.x, r.y);
    uint32_t hi23 = packbf(r.z, r.w);
    uint32_t lo01 = packbf(r.x - hx, r.y - hy);
    uint32_t lo23 = packbf(r.z - hz, r.w - hw);

    size_t obase = (size_t)w * HOUT + h * HH + lane * 4;
    *(uint2*)&d_Agghi[obase] = make_uint2(hi01, hi23);
    *(uint2*)&d_Agglo[obase] = make_uint2(lo01, lo23);
}

// ---------------------------------------------------------------------------
// Tensor-core GEMM + fused epilogue. A is pre-split bf16 (no convert in loop).
// BM=128, BN=128, BK=32, 256 threads, 8 warps as 4(M)x2(N).
// ---------------------------------------------------------------------------
#define SPAD 40
__global__ void __launch_bounds__(256) k_gemm_tc(const float* __restrict__ bias,
                                                 const float* __restrict__ g,
                                                 const float* __restrict__ bparm,
                                                 float* __restrict__ outp,
                                                 int mode) {
    __shared__ __nv_bfloat16 sAhi[128 * SPAD];
    __shared__ __nv_bfloat16 sAlo[128 * SPAD];
    __shared__ __nv_bfloat16 sBhi[128 * SPAD];
    __shared__ __nv_bfloat16 sBlo[128 * SPAD];
    __shared__ float sred[2][2][128];

    const int tid  = threadIdx.x;
    const int lane = tid & 31;
    const int wid  = tid >> 5;
    const int wm   = wid & 3;
    const int wn   = wid >> 2;
    const int brow = blockIdx.x * 128;

    const int lr = tid >> 1;
    const int lk = (tid & 1) * 16;
    const int grow = brow + lr;
    const bool arow_ok = (grow < MTOT);

    float c[2][8][4];
    #pragma unroll
    for (int i = 0; i < 2; i++)
        #pragma unroll
        for (int j = 0; j < 8; j++)
            #pragma unroll
            for (int q = 0; q < 4; q++) c[i][j][q] = 0.f;

    const uint32_t uAhi = s2u(sAhi), uAlo = s2u(sAlo);
    const uint32_t uBhi = s2u(sBhi), uBlo = s2u(sBlo);

    uint4 ah0, ah1, al0, al1;
    uint4 bh0, bh1, bl0, bl1;
    const uint4 z4 = make_uint4(0, 0, 0, 0);

    {
        if (arow_ok) {
            const uint4* pah = (const uint4*)&d_Agghi[(size_t)grow * HOUT + lk];
            const uint4* pal = (const uint4*)&d_Agglo[(size_t)grow * HOUT + lk];
            ah0 = pah[0]; ah1 = pah[1];
            al0 = pal[0]; al1 = pal[1];
        } else {
            ah0 = ah1 = al0 = al1 = z4;
        }
        const uint4* pbh = (const uint4*)&d_WThi[(size_t)lr * HOUT + lk];
        const uint4* pbl = (const uint4*)&d_WTlo[(size_t)lr * HOUT + lk];
        bh0 = pbh[0]; bh1 = pbh[1];
        bl0 = pbl[0]; bl1 = pbl[1];
    }

    #pragma unroll 1
    for (int it = 0; it < HOUT / 32; it++) {
        {
            int so = lr * SPAD + lk;
            *(uint4*)&sAhi[so]     = ah0;
            *(uint4*)&sAhi[so + 8] = ah1;
            *(uint4*)&sAlo[so]     = al0;
            *(uint4*)&sAlo[so + 8] = al1;
            *(uint4*)&sBhi[so]     = bh0;
            *(uint4*)&sBhi[so + 8] = bh1;
            *(uint4*)&sBlo[so]     = bl0;
            *(uint4*)&sBlo[so + 8] = bl1;
        }
        __syncthreads();

        if (it + 1 < HOUT / 32) {
            int k0 = (it + 1) * 32;
            if (arow_ok) {
                const uint4* pah = (const uint4*)&d_Agghi[(size_t)grow * HOUT + k0 + lk];
                const uint4* pal = (const uint4*)&d_Agglo[(size_t)grow * HOUT + k0 + lk];
                ah0 = pah[0]; ah1 = pah[1];
                al0 = pal[0]; al1 = pal[1];
            }
            const uint4* pbh = (const uint4*)&d_WThi[(size_t)lr * HOUT + k0 + lk];
            const uint4* pbl = (const uint4*)&d_WTlo[(size_t)lr * HOUT + k0 + lk];
            bh0 = pbh[0]; bh1 = pbh[1];
            bl0 = pbl[0]; bl1 = pbl[1];
        }

        #pragma unroll
        for (int ks = 0; ks < 2; ks++) {
            const int kk = ks * 16;
            uint32_t ahi[2][4], alo[2][4];
            #pragma unroll
            for (int mt = 0; mt < 2; mt++) {
                int rb = wm * 32 + mt * 16;
                uint32_t off = 2u * ((rb + (lane & 15)) * SPAD + kk + (lane >> 4) * 8);
                ldsm4(ahi[mt], uAhi + off);
                ldsm4(alo[mt], uAlo + off);
            }
            #pragma unroll
            for (int np = 0; np < 4; np++) {
                int cb = wn * 64 + np * 16;
                uint32_t boff = 2u * ((cb + (lane >> 4) * 8 + (lane & 7)) * SPAD
                                      + kk + ((lane >> 3) & 1) * 8);
                uint32_t bh[4], bl[4];
                ldsm4(bh, uBhi + boff);
                ldsm4(bl, uBlo + boff);
                #pragma unroll
                for (int half = 0; half < 2; half++) {
                    int nt = np * 2 + half;
                    #pragma unroll
                    for (int mt = 0; mt < 2; mt++) {
                        mma16816(c[mt][nt], ahi[mt], &bh[half * 2]);
                        mma16816(c[mt][nt], ahi[mt], &bl[half * 2]);
                        mma16816(c[mt][nt], alo[mt], &bh[half * 2]);
                    }
                }
            }
        }
        __syncthreads();
    }

    // ---- fused epilogue ----
    const int colq = (lane & 3) * 2;

    #pragma unroll
    for (int nt = 0; nt < 8; nt++) {
        int col = wn * 64 + nt * 8 + colq;
        float b0 = __ldg(&bias[col]);
        float b1 = __ldg(&bias[col + 1]);
        #pragma unroll
        for (int mt = 0; mt < 2; mt++) {
            c[mt][nt][0] += b0; c[mt][nt][1] += b1;
            c[mt][nt][2] += b0; c[mt][nt][3] += b1;
        }
    }

    if (mode == 1) {
        #pragma unroll
        for (int mt = 0; mt < 2; mt++) {
            #pragma unroll
            for (int nt = 0; nt < 8; nt++) {
                int r0 = brow + wm * 32 + mt * 16 + (lane >> 2);
                int col = wn * 64 + nt * 8 + colq;
                if (r0 < MTOT)
                    *(float2*)&outp[(size_t)r0 * HH + col] = make_float2(c[mt][nt][0], c[mt][nt][1]);
                if (r0 + 8 < MTOT)
                    *(float2*)&outp[(size_t)(r0 + 8) * HH + col] = make_float2(c[mt][nt][2], c[mt][nt][3]);
            }
        }
        return;
    }

    // mean
    #pragma unroll
    for (int mt = 0; mt < 2; mt++) {
        float p0 = 0.f, p1 = 0.f;
        #pragma unroll
        for (int nt = 0; nt < 8; nt++) {
            p0 += c[mt][nt][0] + c[mt][nt][1];
            p1 += c[mt][nt][2] + c[mt][nt][3];
        }
        p0 += __shfl_xor_sync(0xffffffffu, p0, 1);
        p0 += __shfl_xor_sync(0xffffffffu, p0, 2);
        p1 += __shfl_xor_sync(0xffffffffu, p1, 1);
        p1 += __shfl_xor_sync(0xffffffffu, p1, 2);
        if ((lane & 3) == 0) {
            int r = wm * 32 + mt * 16 + (lane >> 2);
            sred[0][wn][r]     = p0;
            sred[0][wn][r + 8] = p1;
        }
    }
    __syncthreads();
    float mu[2][2];
    #pragma unroll
    for (int mt = 0; mt < 2; mt++) {
        int r = wm * 32 + mt * 16 + (lane >> 2);
        mu[mt][0] = (sred[0][0][r]     + sred[0][1][r])     * (1.f / 128.f);
        mu[mt][1] = (sred[0][0][r + 8] + sred[0][1][r + 8]) * (1.f / 128.f);
    }

    // variance
    #pragma unroll
    for (int mt = 0; mt < 2; mt++) {
        float p0 = 0.f, p1 = 0.f;
        #pragma unroll
        for (int nt = 0; nt < 8; nt++) {
            float d0 = c[mt][nt][0] - mu[mt][0];
            float d1 = c[mt][nt][1] - mu[mt][0];
            float d2 = c[mt][nt][2] - mu[mt][1];
            float d3 = c[mt][nt][3] - mu[mt][1];
            p0 += d0 * d0 + d1 * d1;
            p1 += d2 * d2 + d3 * d3;
        }
        p0 += __shfl_xor_sync(0xffffffffu, p0, 1);
        p0 += __shfl_xor_sync(0xffffffffu, p0, 2);
        p1 += __shfl_xor_sync(0xffffffffu, p1, 1);
        p1 += __shfl_xor_sync(0xffffffffu, p1, 2);
        if ((lane & 3) == 0) {
            int r = wm * 32 + mt * 16 + (lane >> 2);
            sred[1][wn][r]     = p0;
            sred[1][wn][r + 8] = p1;
        }
    }
    __syncthreads();
    float rst[2][2];
    #pragma unroll
    for (int mt = 0; mt < 2; mt++) {
        int r = wm * 32 + mt * 16 + (lane >> 2);
        rst[mt][0] = rsqrtf((sred[1][0][r]     + sred[1][1][r])     * (1.f / 128.f) + 1e-5f);
        rst[mt][1] = rsqrtf((sred[1][0][r + 8] + sred[1][1][r + 8]) * (1.f / 128.f) + 1e-5f);
    }

    // normalize + ReLU + store
    #pragma unroll
    for (int nt = 0; nt < 8; nt++) {
        int col = wn * 64 + nt * 8 + colq;
        float g0 = __ldg(&g[col]),      g1 = __ldg(&g[col + 1]);
        float q0 = __ldg(&bparm[col]),  q1 = __ldg(&bparm[col + 1]);
        #pragma unroll
        for (int mt = 0; mt < 2; mt++) {
            int r0 = brow + wm * 32 + mt * 16 + (lane >> 2);
            if (r0 < MTOT) {
                float o0 = fmaxf(fmaf((c[mt][nt][0] - mu[mt][0]) * rst[mt][0], g0, q0), 0.f);
                float o1 = fmaxf(fmaf((c[mt][nt][1] - mu[mt][0]) * rst[mt][0], g1, q1), 0.f);
                *(float2*)&d_X[(size_t)r0 * HH + col] = make_float2(o0, o1);
            }
            if (r0 + 8 < MTOT) {
                float o2 = fmaxf(fmaf((c[mt][nt][2] - mu[mt][1]) * rst[mt][1], g0, q0), 0.f);
                float o3 = fmaxf(fmaf((c[mt][nt][3] - mu[mt][1]) * rst[mt][1], g1, q1), 0.f);
                *(float2*)&d_X[(size_t)(r0 + 8) * HH + col] = make_float2(o2, o3);
            }
        }
    }
}

// ---------------------------------------------------------------------------
// Launch
// ---------------------------------------------------------------------------
extern "C" void kernel_launch(void* const* d_in, const int* in_sizes, int n_in,
                              void* d_out, int out_size) {
    const float* x0   = (const float*)d_in[0];
    const int*   src  = (const int*)d_in[1];
    const int*   tgt  = (const int*)d_in[2];
    const float* W1   = (const float*)d_in[3];
    const float* as1  = (const float*)d_in[4];
    const float* ad1  = (const float*)d_in[5];
    const float* b1   = (const float*)d_in[6];
    const float* W2   = (const float*)d_in[7];
    const float* as2  = (const float*)d_in[8];
    const float* ad2  = (const float*)d_in[9];
    const float* b2   = (const float*)d_in[10];
    const float* W3   = (const float*)d_in[11];
    const float* as3  = (const float*)d_in[12];
    const float* ad3  = (const float*)d_in[13];
    const float* b3   = (const float*)d_in[14];
    const float* g1   = (const float*)d_in[15];
    const float* bb1  = (const float*)d_in[16];
    const float* g2   = (const float*)d_in[17];
    const float* bb2  = (const float*)d_in[18];
    float* out = (float*)d_out;

    float* d_X_ptr;
    cudaGetSymbolAddress((void**)&d_X_ptr, d_X);

    // ---- CSR build ----
    k_zero_cnt<<<(BB * (NN + 1) + 255) / 256, 256>>>();
    k_hist<<<(BB * EE + 255) / 256, 256>>>(tgt);
    k_scan<<<BB, 1024>>>();
    k_scatter<<<(BB * EE + 255) / 256, 256>>>(src, tgt);

    const int gw = MTOT / 8;
    const int gm = (MTOT + 127) / 128;

    // ---- Layer 1 ----
    k_prep<<<20, 256>>>(W1, as1, ad1);
    k_escore<<<gw, 256>>>(x0);
    k_alpha<<<gw, 256>>>();
    k_gather<<<MTOT, 128>>>(x0);
    k_gemm_tc<<<gm, 256>>>(b1, g1, bb1, nullptr, 0);

    // ---- Layer 2 ----
    k_prep<<<20, 256>>>(W2, as2, ad2);
    k_escore<<<gw, 256>>>(d_X_ptr);
    k_alpha<<<gw, 256>>>();
    k_gather<<<MTOT, 128>>>(d_X_ptr);
    k_gemm_tc<<<gm, 256>>>(b2, g2, bb2, nullptr, 0);

    // ---- Layer 3 ----
    k_prep<<<20, 256>>>(W3, as3, ad3);
    k_escore<<<gw, 256>>>(d_X_ptr);
    k_alpha<<<gw, 256>>>();
    k_gather<<<MTOT, 128>>>(d_X_ptr);
    k_gemm_tc<<<gm, 256>>>(b3, nullptr, nullptr, out, 1);
}

// round 13
// speedup vs baseline: 1.1324x; 1.0820x over previous
#include <cuda_runtime.h>
#include <cuda_bf16.h>
#include <cstdint>

// Problem constants
#define BB      4
#define NN      10000
#define EE      160000
#define HH      128
#define NHEADS  4
#define HOUT    512      // NHEADS * HH
#define MTOT    (BB*NN)  // 40000 rows

// ---------------------------------------------------------------------------
// Static device scratch
// ---------------------------------------------------------------------------
__device__ __nv_bfloat16 d_Agghi[(size_t)BB * NN * HOUT]; // aggregated X, bf16 hi
__device__ __nv_bfloat16 d_Agglo[(size_t)BB * NN * HOUT]; // aggregated X, bf16 lo
__device__ float d_X[(size_t)BB * NN * HH];         // layer activations  [B*N, 128]
__device__ float d_esrc[BB * NN * NHEADS];
__device__ float d_edst[BB * NN * NHEADS];
__device__ float d_alpha[(size_t)BB * EE * NHEADS]; // normalized softmax weights
__device__ float d_aself[BB * NN * NHEADS];         // normalized self weights
__device__ int   d_cnt[BB * (NN + 1)];
__device__ int   d_off[BB * (NN + 1)];
__device__ int   d_cur[BB * NN];
__device__ int   d_es [BB * EE];
__device__ float d_Ws[HH * NHEADS];
__device__ float d_Wd[HH * NHEADS];
__device__ __nv_bfloat16 d_WThi[HH * HOUT];         // W^T split, [c=128][k=512], 0.25 folded
__device__ __nv_bfloat16 d_WTlo[HH * HOUT];

__device__ __forceinline__ float lrelu(float x) { return x > 0.f ? x : 0.2f * x; }

__device__ __forceinline__ uint32_t s2u(const void* p) {
    return (uint32_t)__cvta_generic_to_shared(p);
}
__device__ __forceinline__ uint32_t packbf(float x, float y) {
    __nv_bfloat162 t = __floats2bfloat162_rn(x, y);
    return *(uint32_t*)&t;
}
__device__ __forceinline__ void ldsm4(uint32_t* r, uint32_t addr) {
    asm volatile("ldmatrix.sync.aligned.m8n8.x4.shared.b16 {%0,%1,%2,%3}, [%4];\n"
                 : "=r"(r[0]), "=r"(r[1]), "=r"(r[2]), "=r"(r[3]) : "r"(addr));
}
__device__ __forceinline__ void mma16816(float* c, const uint32_t* a, const uint32_t* b) {
    asm volatile("mma.sync.aligned.m16n8k16.row.col.f32.bf16.bf16.f32 "
                 "{%0,%1,%2,%3}, {%4,%5,%6,%7}, {%8,%9}, {%0,%1,%2,%3};\n"
                 : "+f"(c[0]), "+f"(c[1]), "+f"(c[2]), "+f"(c[3])
                 : "r"(a[0]), "r"(a[1]), "r"(a[2]), "r"(a[3]), "r"(b[0]), "r"(b[1]));
}

// ---------------------------------------------------------------------------
// CSR build
// ---------------------------------------------------------------------------
__global__ void k_zero_cnt() {
    int i = blockIdx.x * blockDim.x + threadIdx.x;
    if (i < BB * (NN + 1)) d_cnt[i] = 0;
}
__global__ void k_hist(const int* __restrict__ tgt) {
    int e = blockIdx.x * blockDim.x + threadIdx.x;
    if (e < BB * EE) {
        int b = e / EE;
        atomicAdd(&d_cnt[b * (NN + 1) + tgt[e]], 1);
    }
}
__global__ void k_scan() {
    int b = blockIdx.x;
    __shared__ int sh[1024];
    __shared__ int s_run;
    int tid = threadIdx.x;
    if (tid == 0) s_run = 0;
    __syncthreads();
    for (int base = 0; base < NN; base += 1024) {
        int idx = base + tid;
        int c = (idx < NN) ? d_cnt[b * (NN + 1) + idx] : 0;
        sh[tid] = c;
        __syncthreads();
        #pragma unroll
        for (int st = 1; st < 1024; st <<= 1) {
            int v = (tid >= st) ? sh[tid - st] : 0;
            __syncthreads();
            sh[tid] += v;
            __syncthreads();
        }
        int run = s_run;
        if (idx < NN) {
            int excl = run + sh[tid] - c;
            d_off[b * (NN + 1) + idx] = excl;
            d_cur[b * NN + idx]       = excl;
        }
        __syncthreads();
        if (tid == 1023) s_run = run + sh[1023];
        __syncthreads();
    }
    if (tid == 0) d_off[b * (NN + 1) + NN] = s_run;
}
__global__ void k_scatter(const int* __restrict__ src, const int* __restrict__ tgt) {
    int e = blockIdx.x * blockDim.x + threadIdx.x;
    if (e < BB * EE) {
        int b = e / EE;
        int t = tgt[e];
        int p = atomicAdd(&d_cur[b * NN + t], 1);
        d_es[(size_t)b * EE + p] = src[e];
    }
}

// ---------------------------------------------------------------------------
// Merged per-layer prep:
//  blocks 0..15  : bf16 split of 0.25*W^T
//  blocks 16..19 : attention projection vectors
// ---------------------------------------------------------------------------
__global__ void __launch_bounds__(256) k_prep(const float* __restrict__ W,
                                              const float* __restrict__ as_,
                                              const float* __restrict__ ad_) {
    int blk = blockIdx.x;
    int t = threadIdx.x;
    if (blk < 16) {
        int c = blk * 8 + (t >> 5);
        int kb = (t & 31) * 16;
        __nv_bfloat16 hi[16], lo[16];
        #pragma unroll
        for (int i = 0; i < 16; i++) {
            int k = kb + i;
            float val = 0.25f * W[(size_t)(k & 127) * HOUT + (k >> 7) * HH + c];
            __nv_bfloat16 h = __float2bfloat16_rn(val);
            hi[i] = h;
            lo[i] = __float2bfloat16_rn(val - __bfloat162float(h));
        }
        size_t base = (size_t)c * HOUT + kb;
        *(uint4*)&d_WThi[base]     = *(uint4*)&hi[0];
        *(uint4*)&d_WThi[base + 8] = *(uint4*)&hi[8];
        *(uint4*)&d_WTlo[base]     = *(uint4*)&lo[0];
        *(uint4*)&d_WTlo[base + 8] = *(uint4*)&lo[8];
    } else {
        int tt = (blk - 16) * 256 + t;       // 0..1023
        int c = tt >> 3;
        int q = tt & 7;
        int h = q & 3;
        bool is_d = (q >= 4);
        const float* a = is_d ? ad_ : as_;
        float sum = 0.f;
        const float* wr = W + (size_t)c * HOUT + h * HH;
        const float* ar = a + h * HH;
        #pragma unroll 8
        for (int k = 0; k < HH; k++) sum = fmaf(wr[k], ar[k], sum);
        if (is_d) d_Wd[c * NHEADS + h] = sum;
        else      d_Ws[c * NHEADS + h] = sum;
    }
}

// ---------------------------------------------------------------------------
// escore: warp per row
// ---------------------------------------------------------------------------
__global__ void __launch_bounds__(256) k_escore(const float* __restrict__ Xin) {
    __shared__ float sWs[HH * NHEADS];
    __shared__ float sWd[HH * NHEADS];
    int tid = threadIdx.x;
    sWs[tid] = d_Ws[tid]; sWs[tid + 256] = d_Ws[tid + 256];
    sWd[tid] = d_Wd[tid]; sWd[tid + 256] = d_Wd[tid + 256];
    __syncthreads();

    int row = blockIdx.x * 8 + (tid >> 5);
    int lane = tid & 31;
    float4 x = *(const float4*)&Xin[(size_t)row * HH + lane * 4];
    float xv[4] = {x.x, x.y, x.z, x.w};
    float p[8] = {0, 0, 0, 0, 0, 0, 0, 0};
    #pragma unroll
    for (int i = 0; i < 4; i++) {
        int c = lane * 4 + i;
        #pragma unroll
        for (int h = 0; h < 4; h++) {
            p[h]     = fmaf(xv[i], sWs[c * 4 + h], p[h]);
            p[4 + h] = fmaf(xv[i], sWd[c * 4 + h], p[4 + h]);
        }
    }
    #pragma unroll
    for (int s = 16; s > 0; s >>= 1) {
        #pragma unroll
        for (int q = 0; q < 8; q++)
            p[q] += __shfl_xor_sync(0xffffffffu, p[q], s);
    }
    if (lane == 0) {
        *(float4*)&d_esrc[row * 4] = make_float4(p[0], p[1], p[2], p[3]);
        *(float4*)&d_edst[row * 4] = make_float4(p[4], p[5], p[6], p[7]);
    }
}

// ---------------------------------------------------------------------------
// alpha: warp per node. 3 streamed passes (R7/R12-proven structure).
// ---------------------------------------------------------------------------
__global__ void __launch_bounds__(256) k_alpha() {
    int w = blockIdx.x * 8 + (threadIdx.x >> 5);
    int lane = threadIdx.x & 31;
    int b = w / NN;
    int n = w - b * NN;
    const int beg = d_off[b * (NN + 1) + n];
    const int cnte = d_off[b * (NN + 1) + n + 1] - beg;
    const size_t ebase = (size_t)b * EE + beg;

    float4 ed4 = *(const float4*)&d_edst[w * 4];
    float edv[4] = {ed4.x, ed4.y, ed4.z, ed4.w};
    float4 es4 = *(const float4*)&d_esrc[w * 4];
    float esf[4] = {es4.x, es4.y, es4.z, es4.w};
    float e_self[4];
    #pragma unroll
    for (int h = 0; h < 4; h++) e_self[h] = lrelu(esf[h] + edv[h]);

    // pass 1: max
    float mx[4] = {e_self[0], e_self[1], e_self[2], e_self[3]};
    for (int j = lane; j < cnte; j += 32) {
        int src = __ldg(&d_es[ebase + j]);
        float4 e4 = __ldg((const float4*)&d_esrc[((size_t)b * NN + src) * 4]);
        float ev[4] = {e4.x, e4.y, e4.z, e4.w};
        #pragma unroll
        for (int h = 0; h < 4; h++) mx[h] = fmaxf(mx[h], lrelu(ev[h] + edv[h]));
    }
    #pragma unroll
    for (int s = 16; s > 0; s >>= 1)
        #pragma unroll
        for (int h = 0; h < 4; h++) mx[h] = fmaxf(mx[h], __shfl_xor_sync(0xffffffffu, mx[h], s));

    // pass 2: exp, store to d_alpha, accumulate sum
    float sm[4] = {0, 0, 0, 0};
    for (int j = lane; j < cnte; j += 32) {
        int src = __ldg(&d_es[ebase + j]);
        float4 e4 = __ldg((const float4*)&d_esrc[((size_t)b * NN + src) * 4]);
        float ev[4] = {e4.x, e4.y, e4.z, e4.w};
        float ex[4];
        #pragma unroll
        for (int h = 0; h < 4; h++) {
            ex[h] = __expf(lrelu(ev[h] + edv[h]) - mx[h]);
            sm[h] += ex[h];
        }
        *(float4*)&d_alpha[(ebase + j) * 4] = make_float4(ex[0], ex[1], ex[2], ex[3]);
    }
    #pragma unroll
    for (int s = 16; s > 0; s >>= 1)
        #pragma unroll
        for (int h = 0; h < 4; h++) sm[h] += __shfl_xor_sync(0xffffffffu, sm[h], s);

    float ex_self[4], inv[4];
    #pragma unroll
    for (int h = 0; h < 4; h++) {
        ex_self[h] = __expf(e_self[h] - mx[h]);
        inv[h] = 1.f / (sm[h] + ex_self[h]);
    }
    float4 invv = make_float4(inv[0], inv[1], inv[2], inv[3]);

    // pass 3: rescale stored exps
    for (int j = lane; j < cnte; j += 32) {
        float4 a = *(const float4*)&d_alpha[(ebase + j) * 4];
        a.x *= invv.x; a.y *= invv.y; a.z *= invv.z; a.w *= invv.w;
        *(float4*)&d_alpha[(ebase + j) * 4] = a;
    }
    if (lane == 0)
        *(float4*)&d_aself[w * 4] = make_float4(ex_self[0] * invv.x, ex_self[1] * invv.y,
                                                ex_self[2] * invv.z, ex_self[3] * invv.w);
}

// ---------------------------------------------------------------------------
// gather: WARP per node (8 nodes / 256-thread block, grid 5000).
// No cross-warp reduction, no __syncthreads, 8x less block overhead.
// Lane owns 4 channels (float4); alpha float4 is a warp-broadcast load.
// Writes bf16 hi/lo split (same rounding as in-GEMM split).
// ---------------------------------------------------------------------------
__global__ void __launch_bounds__(256) k_gather(const float* __restrict__ Xin) {
    const int w = blockIdx.x * 8 + (threadIdx.x >> 5);   // node id
    const int lane = threadIdx.x & 31;
    const int b = w / NN;
    const int n = w - b * NN;
    const int beg = d_off[b * (NN + 1) + n];
    const int cnte = d_off[b * (NN + 1) + n + 1] - beg;
    const size_t ebase = (size_t)b * EE + beg;
    const float* Xb = Xin + (size_t)b * NN * HH;

    // self-loop init
    float4 as_ = __ldg((const float4*)&d_aself[w * 4]);
    float4 xs = __ldg((const float4*)&Xb[(size_t)n * HH + lane * 4]);
    float4 a0, a1, a2, a3;
    a0.x = as_.x * xs.x; a0.y = as_.x * xs.y; a0.z = as_.x * xs.z; a0.w = as_.x * xs.w;
    a1.x = as_.y * xs.x; a1.y = as_.y * xs.y; a1.z = as_.y * xs.z; a1.w = as_.y * xs.w;
    a2.x = as_.z * xs.x; a2.y = as_.z * xs.y; a2.z = as_.z * xs.z; a2.w = as_.z * xs.w;
    a3.x = as_.w * xs.x; a3.y = as_.w * xs.y; a3.z = as_.w * xs.z; a3.w = as_.w * xs.w;

    #pragma unroll 4
    for (int j = 0; j < cnte; j++) {
        int src = __ldg(&d_es[ebase + j]);                               // broadcast
        float4 al = __ldg((const float4*)&d_alpha[(ebase + j) * 4]);     // broadcast
        float4 x = __ldg((const float4*)&Xb[(size_t)src * HH + lane * 4]); // coalesced 512B
        a0.x = fmaf(al.x, x.x, a0.x); a0.y = fmaf(al.x, x.y, a0.y);
        a0.z = fmaf(al.x, x.z, a0.z); a0.w = fmaf(al.x, x.w, a0.w);
        a1.x = fmaf(al.y, x.x, a1.x); a1.y = fmaf(al.y, x.y, a1.y);
        a1.z = fmaf(al.y, x.z, a1.z); a1.w = fmaf(al.y, x.w, a1.w);
        a2.x = fmaf(al.z, x.x, a2.x); a2.y = fmaf(al.z, x.y, a2.y);
        a2.z = fmaf(al.z, x.z, a2.z); a2.w = fmaf(al.z, x.w, a2.w);
        a3.x = fmaf(al.w, x.x, a3.x); a3.y = fmaf(al.w, x.y, a3.y);
        a3.z = fmaf(al.w, x.z, a3.z); a3.w = fmaf(al.w, x.w, a3.w);
    }

    // bf16 hi/lo split write, per head
    size_t obase = (size_t)w * HOUT + lane * 4;
    float4 acc[4] = {a0, a1, a2, a3};
    #pragma unroll
    for (int h = 0; h < 4; h++) {
        float4 r = acc[h];
        float hx = __bfloat162float(__float2bfloat16_rn(r.x));
        float hy = __bfloat162float(__float2bfloat16_rn(r.y));
        float hz = __bfloat162float(__float2bfloat16_rn(r.z));
        float hw = __bfloat162float(__float2bfloat16_rn(r.w));
        uint32_t hi01 = packbf(r.x, r.y);
        uint32_t hi23 = packbf(r.z, r.w);
        uint32_t lo01 = packbf(r.x - hx, r.y - hy);
        uint32_t lo23 = packbf(r.z - hz, r.w - hw);
        *(uint2*)&d_Agghi[obase + h * HH] = make_uint2(hi01, hi23);
        *(uint2*)&d_Agglo[obase + h * HH] = make_uint2(lo01, lo23);
    }
}

// ---------------------------------------------------------------------------
// Tensor-core GEMM + fused epilogue. A is pre-split bf16 (no convert in loop).
// BM=128, BN=128, BK=32, 256 threads, 8 warps as 4(M)x2(N).
// ---------------------------------------------------------------------------
#define SPAD 40
__global__ void __launch_bounds__(256) k_gemm_tc(const float* __restrict__ bias,
                                                 const float* __restrict__ g,
                                                 const float* __restrict__ bparm,
                                                 float* __restrict__ outp,
                                                 int mode) {
    __shared__ __nv_bfloat16 sAhi[128 * SPAD];
    __shared__ __nv_bfloat16 sAlo[128 * SPAD];
    __shared__ __nv_bfloat16 sBhi[128 * SPAD];
    __shared__ __nv_bfloat16 sBlo[128 * SPAD];
    __shared__ float sred[2][2][128];

    const int tid  = threadIdx.x;
    const int lane = tid & 31;
    const int wid  = tid >> 5;
    const int wm   = wid & 3;
    const int wn   = wid >> 2;
    const int brow = blockIdx.x * 128;

    const int lr = tid >> 1;
    const int lk = (tid & 1) * 16;
    const int grow = brow + lr;
    const bool arow_ok = (grow < MTOT);

    float c[2][8][4];
    #pragma unroll
    for (int i = 0; i < 2; i++)
        #pragma unroll
        for (int j = 0; j < 8; j++)
            #pragma unroll
            for (int q = 0; q < 4; q++) c[i][j][q] = 0.f;

    const uint32_t uAhi = s2u(sAhi), uAlo = s2u(sAlo);
    const uint32_t uBhi = s2u(sBhi), uBlo = s2u(sBlo);

    uint4 ah0, ah1, al0, al1;
    uint4 bh0, bh1, bl0, bl1;
    const uint4 z4 = make_uint4(0, 0, 0, 0);

    {
        if (arow_ok) {
            const uint4* pah = (const uint4*)&d_Agghi[(size_t)grow * HOUT + lk];
            const uint4* pal = (const uint4*)&d_Agglo[(size_t)grow * HOUT + lk];
            ah0 = pah[0]; ah1 = pah[1];
            al0 = pal[0]; al1 = pal[1];
        } else {
            ah0 = ah1 = al0 = al1 = z4;
        }
        const uint4* pbh = (const uint4*)&d_WThi[(size_t)lr * HOUT + lk];
        const uint4* pbl = (const uint4*)&d_WTlo[(size_t)lr * HOUT + lk];
        bh0 = pbh[0]; bh1 = pbh[1];
        bl0 = pbl[0]; bl1 = pbl[1];
    }

    #pragma unroll 1
    for (int it = 0; it < HOUT / 32; it++) {
        {
            int so = lr * SPAD + lk;
            *(uint4*)&sAhi[so]     = ah0;
            *(uint4*)&sAhi[so + 8] = ah1;
            *(uint4*)&sAlo[so]     = al0;
            *(uint4*)&sAlo[so + 8] = al1;
            *(uint4*)&sBhi[so]     = bh0;
            *(uint4*)&sBhi[so + 8] = bh1;
            *(uint4*)&sBlo[so]     = bl0;
            *(uint4*)&sBlo[so + 8] = bl1;
        }
        __syncthreads();

        if (it + 1 < HOUT / 32) {
            int k0 = (it + 1) * 32;
            if (arow_ok) {
                const uint4* pah = (const uint4*)&d_Agghi[(size_t)grow * HOUT + k0 + lk];
                const uint4* pal = (const uint4*)&d_Agglo[(size_t)grow * HOUT + k0 + lk];
                ah0 = pah[0]; ah1 = pah[1];
                al0 = pal[0]; al1 = pal[1];
            }
            const uint4* pbh = (const uint4*)&d_WThi[(size_t)lr * HOUT + k0 + lk];
            const uint4* pbl = (const uint4*)&d_WTlo[(size_t)lr * HOUT + k0 + lk];
            bh0 = pbh[0]; bh1 = pbh[1];
            bl0 = pbl[0]; bl1 = pbl[1];
        }

        #pragma unroll
        for (int ks = 0; ks < 2; ks++) {
            const int kk = ks * 16;
            uint32_t ahi[2][4], alo[2][4];
            #pragma unroll
            for (int mt = 0; mt < 2; mt++) {
                int rb = wm * 32 + mt * 16;
                uint32_t off = 2u * ((rb + (lane & 15)) * SPAD + kk + (lane >> 4) * 8);
                ldsm4(ahi[mt], uAhi + off);
                ldsm4(alo[mt], uAlo + off);
            }
            #pragma unroll
            for (int np = 0; np < 4; np++) {
                int cb = wn * 64 + np * 16;
                uint32_t boff = 2u * ((cb + (lane >> 4) * 8 + (lane & 7)) * SPAD
                                      + kk + ((lane >> 3) & 1) * 8);
                uint32_t bh[4], bl[4];
                ldsm4(bh, uBhi + boff);
                ldsm4(bl, uBlo + boff);
                #pragma unroll
                for (int half = 0; half < 2; half++) {
                    int nt = np * 2 + half;
                    #pragma unroll
                    for (int mt = 0; mt < 2; mt++) {
                        mma16816(c[mt][nt], ahi[mt], &bh[half * 2]);
                        mma16816(c[mt][nt], ahi[mt], &bl[half * 2]);
                        mma16816(c[mt][nt], alo[mt], &bh[half * 2]);
                    }
                }
            }
        }
        __syncthreads();
    }

    // ---- fused epilogue ----
    const int colq = (lane & 3) * 2;

    #pragma unroll
    for (int nt = 0; nt < 8; nt++) {
        int col = wn * 64 + nt * 8 + colq;
        float b0 = __ldg(&bias[col]);
        float b1 = __ldg(&bias[col + 1]);
        #pragma unroll
        for (int mt = 0; mt < 2; mt++) {
            c[mt][nt][0] += b0; c[mt][nt][1] += b1;
            c[mt][nt][2] += b0; c[mt][nt][3] += b1;
        }
    }

    if (mode == 1) {
        #pragma unroll
        for (int mt = 0; mt < 2; mt++) {
            #pragma unroll
            for (int nt = 0; nt < 8; nt++) {
                int r0 = brow + wm * 32 + mt * 16 + (lane >> 2);
                int col = wn * 64 + nt * 8 + colq;
                if (r0 < MTOT)
                    *(float2*)&outp[(size_t)r0 * HH + col] = make_float2(c[mt][nt][0], c[mt][nt][1]);
                if (r0 + 8 < MTOT)
                    *(float2*)&outp[(size_t)(r0 + 8) * HH + col] = make_float2(c[mt][nt][2], c[mt][nt][3]);
            }
        }
        return;
    }

    // mean
    #pragma unroll
    for (int mt = 0; mt < 2; mt++) {
        float p0 = 0.f, p1 = 0.f;
        #pragma unroll
        for (int nt = 0; nt < 8; nt++) {
            p0 += c[mt][nt][0] + c[mt][nt][1];
            p1 += c[mt][nt][2] + c[mt][nt][3];
        }
        p0 += __shfl_xor_sync(0xffffffffu, p0, 1);
        p0 += __shfl_xor_sync(0xffffffffu, p0, 2);
        p1 += __shfl_xor_sync(0xffffffffu, p1, 1);
        p1 += __shfl_xor_sync(0xffffffffu, p1, 2);
        if ((lane & 3) == 0) {
            int r = wm * 32 + mt * 16 + (lane >> 2);
            sred[0][wn][r]     = p0;
            sred[0][wn][r + 8] = p1;
        }
    }
    __syncthreads();
    float mu[2][2];
    #pragma unroll
    for (int mt = 0; mt < 2; mt++) {
        int r = wm * 32 + mt * 16 + (lane >> 2);
        mu[mt][0] = (sred[0][0][r]     + sred[0][1][r])     * (1.f / 128.f);
        mu[mt][1] = (sred[0][0][r + 8] + sred[0][1][r + 8]) * (1.f / 128.f);
    }

    // variance
    #pragma unroll
    for (int mt = 0; mt < 2; mt++) {
        float p0 = 0.f, p1 = 0.f;
        #pragma unroll
        for (int nt = 0; nt < 8; nt++) {
            float d0 = c[mt][nt][0] - mu[mt][0];
            float d1 = c[mt][nt][1] - mu[mt][0];
            float d2 = c[mt][nt][2] - mu[mt][1];
            float d3 = c[mt][nt][3] - mu[mt][1];
            p0 += d0 * d0 + d1 * d1;
            p1 += d2 * d2 + d3 * d3;
        }
        p0 += __shfl_xor_sync(0xffffffffu, p0, 1);
        p0 += __shfl_xor_sync(0xffffffffu, p0, 2);
        p1 += __shfl_xor_sync(0xffffffffu, p1, 1);
        p1 += __shfl_xor_sync(0xffffffffu, p1, 2);
        if ((lane & 3) == 0) {
            int r = wm * 32 + mt * 16 + (lane >> 2);
            sred[1][wn][r]     = p0;
            sred[1][wn][r + 8] = p1;
        }
    }
    __syncthreads();
    float rst[2][2];
    #pragma unroll
    for (int mt = 0; mt < 2; mt++) {
        int r = wm * 32 + mt * 16 + (lane >> 2);
        rst[mt][0] = rsqrtf((sred[1][0][r]     + sred[1][1][r])     * (1.f / 128.f) + 1e-5f);
        rst[mt][1] = rsqrtf((sred[1][0][r + 8] + sred[1][1][r + 8]) * (1.f / 128.f) + 1e-5f);
    }

    // normalize + ReLU + store
    #pragma unroll
    for (int nt = 0; nt < 8; nt++) {
        int col = wn * 64 + nt * 8 + colq;
        float g0 = __ldg(&g[col]),      g1 = __ldg(&g[col + 1]);
        float q0 = __ldg(&bparm[col]),  q1 = __ldg(&bparm[col + 1]);
        #pragma unroll
        for (int mt = 0; mt < 2; mt++) {
            int r0 = brow + wm * 32 + mt * 16 + (lane >> 2);
            if (r0 < MTOT) {
                float o0 = fmaxf(fmaf((c[mt][nt][0] - mu[mt][0]) * rst[mt][0], g0, q0), 0.f);
                float o1 = fmaxf(fmaf((c[mt][nt][1] - mu[mt][0]) * rst[mt][0], g1, q1), 0.f);
                *(float2*)&d_X[(size_t)r0 * HH + col] = make_float2(o0, o1);
            }
            if (r0 + 8 < MTOT) {
                float o2 = fmaxf(fmaf((c[mt][nt][2] - mu[mt][1]) * rst[mt][1], g0, q0), 0.f);
                float o3 = fmaxf(fmaf((c[mt][nt][3] - mu[mt][1]) * rst[mt][1], g1, q1), 0.f);
                *(float2*)&d_X[(size_t)(r0 + 8) * HH + col] = make_float2(o2, o3);
            }
        }
    }
}

// ---------------------------------------------------------------------------
// Launch
// ---------------------------------------------------------------------------
extern "C" void kernel_launch(void* const* d_in, const int* in_sizes, int n_in,
                              void* d_out, int out_size) {
    const float* x0   = (const float*)d_in[0];
    const int*   src  = (const int*)d_in[1];
    const int*   tgt  = (const int*)d_in[2];
    const float* W1   = (const float*)d_in[3];
    const float* as1  = (const float*)d_in[4];
    const float* ad1  = (const float*)d_in[5];
    const float* b1   = (const float*)d_in[6];
    const float* W2   = (const float*)d_in[7];
    const float* as2  = (const float*)d_in[8];
    const float* ad2  = (const float*)d_in[9];
    const float* b2   = (const float*)d_in[10];
    const float* W3   = (const float*)d_in[11];
    const float* as3  = (const float*)d_in[12];
    const float* ad3  = (const float*)d_in[13];
    const float* b3   = (const float*)d_in[14];
    const float* g1   = (const float*)d_in[15];
    const float* bb1  = (const float*)d_in[16];
    const float* g2   = (const float*)d_in[17];
    const float* bb2  = (const float*)d_in[18];
    float* out = (float*)d_out;

    float* d_X_ptr;
    cudaGetSymbolAddress((void**)&d_X_ptr, d_X);

    // ---- CSR build ----
    k_zero_cnt<<<(BB * (NN + 1) + 255) / 256, 256>>>();
    k_hist<<<(BB * EE + 255) / 256, 256>>>(tgt);
    k_scan<<<BB, 1024>>>();
    k_scatter<<<(BB * EE + 255) / 256, 256>>>(src, tgt);

    const int gw = MTOT / 8;             // warp-per-node grids (5000)
    const int gm = (MTOT + 127) / 128;

    // ---- Layer 1 ----
    k_prep<<<20, 256>>>(W1, as1, ad1);
    k_escore<<<gw, 256>>>(x0);
    k_alpha<<<gw, 256>>>();
    k_gather<<<gw, 256>>>(x0);
    k_gemm_tc<<<gm, 256>>>(b1, g1, bb1, nullptr, 0);

    // ---- Layer 2 ----
    k_prep<<<20, 256>>>(W2, as2, ad2);
    k_escore<<<gw, 256>>>(d_X_ptr);
    k_alpha<<<gw, 256>>>();
    k_gather<<<gw, 256>>>(d_X_ptr);
    k_gemm_tc<<<gm, 256>>>(b2, g2, bb2, nullptr, 0);

    // ---- Layer 3 ----
    k_prep<<<20, 256>>>(W3, as3, ad3);
    k_escore<<<gw, 256>>>(d_X_ptr);
    k_alpha<<<gw, 256>>>();
    k_gather<<<gw, 256>>>(d_X_ptr);
    k_gemm_tc<<<gm, 256>>>(b3, nullptr, nullptr, out, 1);
}